// round 15
// baseline (speedup 1.0000x reference)
#include <cuda_runtime.h>

// RLGate: B=4, T=2048, D=1024, E=8, K=2
// Warp-autonomous, 2 tokens/warp, batched phase-1 loads, hoisted select-path
// loads, interleaved dual reduction + CROSS-TOKEN pipelined gather (in-flight
// never drains between tokens). 32-bit addressing throughout.

#define BB      4
#define TT      2048
#define DD      1024
#define EE      8
#define NTOK    (BB * TT)          // 8192
#define TPB_TOK 16                  // tokens per CTA (8 warps x 2)
#define NCTA    (NTOK / TPB_TOK)    // 512
#define EPSF    1e-9f
#define FULLM   0xFFFFFFFFu

__device__ float g_contrib[NCTA];
__device__ int   g_count = 0;

__global__ __launch_bounds__(256, 4) void rlgate_kernel(
    const float* __restrict__ x,
    const float* __restrict__ eo,
    const float* __restrict__ rewards,
    const float* __restrict__ W,
    const float* __restrict__ bias,
    const float* __restrict__ baseline,
    const float* __restrict__ noise_u,
    float* __restrict__ out)
{
    const int tid  = threadIdx.x;
    const int lane = tid & 31;
    const int warp = tid >> 5;

    __shared__ __align__(16) float Wt[EE][1024];   // transposed W
    __shared__ float bias_s[EE];
    __shared__ float contrib_s[8];

    // ---- this warp's 2 tokens; per-lane select-phase ids known up front ----
    const int t0  = blockIdx.x * TPB_TOK + warp * 2;   // t1 = t0 + 1
    const int e   = lane & 7;
    const int grp = (lane >> 3) & 1;                   // 0 -> t0, 1 -> t1
    const int tok = t0 + grp;

    // hoist critical-path gmem loads: overlap with W staging + x batches
    const float u_raw = noise_u[tok * EE + e];
    const float rew   = rewards[tok];
    const float bval  = baseline[0];

    // ---- stage W -> smem transposed (coalesced) ----
    const float4* W4 = reinterpret_cast<const float4*>(W);   // 2048 float4
    #pragma unroll
    for (int k = 0; k < 8; k++) {
        int idx = tid + 256 * k;
        float4 wv = W4[idx];
        int d  = idx >> 1;
        int e0 = (idx & 1) * 4;
        Wt[e0 + 0][d] = wv.x;
        Wt[e0 + 1][d] = wv.y;
        Wt[e0 + 2][d] = wv.z;
        Wt[e0 + 3][d] = wv.w;
    }
    if (tid < EE) bias_s[tid] = bias[tid];
    __syncthreads();

    const float4* X4 = reinterpret_cast<const float4*>(x);
    const int xbaseA = t0 * (DD / 4) + lane;           // fits in 32-bit
    const int xbaseB = xbaseA + (DD / 4);

    float acc0[EE], acc1[EE];
    #pragma unroll
    for (int ee = 0; ee < EE; ee++) { acc0[ee] = 0.0f; acc1[ee] = 0.0f; }

    // two half-row batches: 8 loads in flight, then consume with shared W
    #pragma unroll
    for (int h = 0; h < 2; h++) {
        float4 xa[4], xb[4];
        #pragma unroll
        for (int q = 0; q < 4; q++) {
            xa[q] = __ldcs(&X4[xbaseA + 32 * (4 * h + q)]);
            xb[q] = __ldcs(&X4[xbaseB + 32 * (4 * h + q)]);
        }
        #pragma unroll
        for (int q = 0; q < 4; q++) {
            const int k = 4 * h + q;
            #pragma unroll
            for (int ee = 0; ee < EE; ee++) {
                const float4 w = *reinterpret_cast<const float4*>(
                    &Wt[ee][(lane + 32 * k) * 4]);
                float s0 = xa[q].x * w.x;
                s0 = fmaf(xa[q].y, w.y, s0);
                s0 = fmaf(xa[q].z, w.z, s0);
                acc0[ee] = fmaf(xa[q].w, w.w, acc0[ee] + s0);
                float s1 = xb[q].x * w.x;
                s1 = fmaf(xb[q].y, w.y, s1);
                s1 = fmaf(xb[q].z, w.z, s1);
                acc1[ee] = fmaf(xb[q].w, w.w, acc1[ee] + s1);
            }
        }
    }

    // ---- interleaved dual 16-shuffle split reduction (two ILP chains) ----
    {
        #pragma unroll
        for (int ee = 0; ee < EE; ee++) {
            acc0[ee] += __shfl_xor_sync(FULLM, acc0[ee], 16);
            acc1[ee] += __shfl_xor_sync(FULLM, acc1[ee], 16);
        }
        if (lane & 16) {
            acc0[0] = acc0[4]; acc0[1] = acc0[5]; acc0[2] = acc0[6]; acc0[3] = acc0[7];
            acc1[0] = acc1[4]; acc1[1] = acc1[5]; acc1[2] = acc1[6]; acc1[3] = acc1[7];
        }
        #pragma unroll
        for (int i = 0; i < 4; i++) {
            acc0[i] += __shfl_xor_sync(FULLM, acc0[i], 8);
            acc1[i] += __shfl_xor_sync(FULLM, acc1[i], 8);
        }
        if (lane & 8) { acc0[0] = acc0[2]; acc0[1] = acc0[3];
                        acc1[0] = acc1[2]; acc1[1] = acc1[3]; }
        #pragma unroll
        for (int i = 0; i < 2; i++) {
            acc0[i] += __shfl_xor_sync(FULLM, acc0[i], 4);
            acc1[i] += __shfl_xor_sync(FULLM, acc1[i], 4);
        }
        if (lane & 4) { acc0[0] = acc0[1]; acc1[0] = acc1[1]; }
        acc0[0] += __shfl_xor_sync(FULLM, acc0[0], 2);
        acc1[0] += __shfl_xor_sync(FULLM, acc1[0], 2);
        acc0[0] += __shfl_xor_sync(FULLM, acc0[0], 1);
        acc1[0] += __shfl_xor_sync(FULLM, acc1[0], 1);
    }
    const float r0 = acc0[0];    // lane 4e: token0 expert e
    const float r1 = acc1[0];    // lane 4e: token1 expert e

    // redistribute: 8-lane groups; groups {0,2} do token0, {1,3} do token1
    const float l0 = __shfl_sync(FULLM, r0, 4 * e);
    const float l1 = __shfl_sync(FULLM, r1, 4 * e);
    const float logit = (grp ? l1 : l0) + bias_s[e];

    // ---- softmax + gumbel + top-2 within 8-lane group (ALU only) ----
    float mx = logit;
    #pragma unroll
    for (int off = 4; off > 0; off >>= 1)
        mx = fmaxf(mx, __shfl_xor_sync(FULLM, mx, off));
    float p = __expf(logit - mx);
    float ps = p;
    #pragma unroll
    for (int off = 4; off > 0; off >>= 1)
        ps += __shfl_xor_sync(FULLM, ps, off);

    const float lp = logf(p / ps + EPSF);
    const float u  = u_raw * (1.0f - 2e-7f) + 1e-7f;
    const float sc = lp - logf(-logf(u));

    // butterfly top-2 (strict '>' / lowest index)
    float m1 = sc, m2 = -__int_as_float(0x7F800000);
    int   i1 = e,  i2 = 8;
    #pragma unroll
    for (int off = 4; off > 0; off >>= 1) {
        float om1 = __shfl_xor_sync(FULLM, m1, off);
        int   oi1 = __shfl_xor_sync(FULLM, i1, off);
        float om2 = __shfl_xor_sync(FULLM, m2, off);
        int   oi2 = __shfl_xor_sync(FULLM, i2, off);
        const bool aFirst = (m1 > om1) || (m1 == om1 && i1 < oi1);
        float n1, n2; int ni1, ni2;
        if (aFirst) {
            n1 = m1; ni1 = i1;
            const bool s = (m2 > om1) || (m2 == om1 && i2 < oi1);
            n2 = s ? m2 : om1; ni2 = s ? i2 : oi1;
        } else {
            n1 = om1; ni1 = oi1;
            const bool s = (om2 > m1) || (om2 == m1 && oi2 < i1);
            n2 = s ? om2 : m1; ni2 = s ? oi2 : i1;
        }
        m1 = n1; i1 = ni1; m2 = n2; i2 = ni2;
    }

    // selected log-probs (group-local shuffle)
    const int gbase = lane & ~7;
    const float lpA = __shfl_sync(FULLM, lp, gbase + i1);
    const float lpB = __shfl_sync(FULLM, lp, gbase + i2);

    // aux contribution: group leaders (lanes 0 and 8)
    const float adv = rew - bval;
    const float cme = -(adv * (lpA + lpB)) * (1.0f / (float)NTOK);
    const float ct  = __shfl_sync(FULLM, cme, 0) + __shfl_sync(FULLM, cme, 8);
    if (lane == 0) contrib_s[warp] = ct;

    // broadcast the 4 selected indices to the whole warp
    const int ia0 = __shfl_sync(FULLM, i1, 0);
    const int ib0 = __shfl_sync(FULLM, i2, 0);
    const int ia1 = __shfl_sync(FULLM, i1, 8);
    const int ib1 = __shfl_sync(FULLM, i2, 8);

    // ---- gather: cross-token pipeline; in-flight never drains ----
    const float4* EO4 = reinterpret_cast<const float4*>(eo);
    float4* OUT4 = reinterpret_cast<float4*>(out);
    const int rowA0 = (ia0 * NTOK + t0) * (DD / 4) + lane;       // < 2^25
    const int rowB0 = (ib0 * NTOK + t0) * (DD / 4) + lane;
    const int rowA1 = (ia1 * NTOK + t0 + 1) * (DD / 4) + lane;
    const int rowB1 = (ib1 * NTOK + t0 + 1) * (DD / 4) + lane;
    const int rowO0 = t0 * (DD / 4) + lane;
    const int rowO1 = rowO0 + (DD / 4);

    float4 a[4], c4[4], a2[4];
    #pragma unroll
    for (int j = 0; j < 4; j++) a[j]  = __ldcs(&EO4[rowA0 + 32 * j]);
    #pragma unroll
    for (int j = 0; j < 4; j++) c4[j] = __ldcs(&EO4[rowB0 + 32 * j]);
    #pragma unroll
    for (int j = 0; j < 4; j++) a2[j] = __ldcs(&EO4[rowA0 + 128 + 32 * j]);

    // consume t0 chunk0 (a, c4); a2 + upcoming loads fly through it
    #pragma unroll
    for (int j = 0; j < 4; j++) {
        float4 r;
        r.x = (a[j].x + c4[j].x) * 0.5f;
        r.y = (a[j].y + c4[j].y) * 0.5f;
        r.z = (a[j].z + c4[j].z) * 0.5f;
        r.w = (a[j].w + c4[j].w) * 0.5f;
        __stcs(&OUT4[rowO0 + 32 * j], r);
    }
    #pragma unroll
    for (int j = 0; j < 4; j++) c4[j] = __ldcs(&EO4[rowB0 + 128 + 32 * j]);
    #pragma unroll
    for (int j = 0; j < 4; j++) a[j]  = __ldcs(&EO4[rowA1 + 32 * j]);  // t1 c0

    // consume t0 chunk1 (a2, c4); t1 chunk0 a-rows flying
    #pragma unroll
    for (int j = 0; j < 4; j++) {
        float4 r;
        r.x = (a2[j].x + c4[j].x) * 0.5f;
        r.y = (a2[j].y + c4[j].y) * 0.5f;
        r.z = (a2[j].z + c4[j].z) * 0.5f;
        r.w = (a2[j].w + c4[j].w) * 0.5f;
        __stcs(&OUT4[rowO0 + 128 + 32 * j], r);
    }
    #pragma unroll
    for (int j = 0; j < 4; j++) c4[j] = __ldcs(&EO4[rowB1 + 32 * j]);
    #pragma unroll
    for (int j = 0; j < 4; j++) a2[j] = __ldcs(&EO4[rowA1 + 128 + 32 * j]);

    // consume t1 chunk0 (a, c4); t1 chunk1 a-rows flying
    #pragma unroll
    for (int j = 0; j < 4; j++) {
        float4 r;
        r.x = (a[j].x + c4[j].x) * 0.5f;
        r.y = (a[j].y + c4[j].y) * 0.5f;
        r.z = (a[j].z + c4[j].z) * 0.5f;
        r.w = (a[j].w + c4[j].w) * 0.5f;
        __stcs(&OUT4[rowO1 + 32 * j], r);
    }
    #pragma unroll
    for (int j = 0; j < 4; j++) c4[j] = __ldcs(&EO4[rowB1 + 128 + 32 * j]);

    // consume t1 chunk1 (a2, c4)
    #pragma unroll
    for (int j = 0; j < 4; j++) {
        float4 r;
        r.x = (a2[j].x + c4[j].x) * 0.5f;
        r.y = (a2[j].y + c4[j].y) * 0.5f;
        r.z = (a2[j].z + c4[j].z) * 0.5f;
        r.w = (a2[j].w + c4[j].w) * 0.5f;
        __stcs(&OUT4[rowO1 + 128 + 32 * j], r);
    }

    // ---- aux finalize: CTA reduce + last-block global reduce ----
    __syncthreads();
    if (warp == 0) {
        float c = (lane < 8) ? contrib_s[lane] : 0.0f;
        #pragma unroll
        for (int off = 4; off > 0; off >>= 1)
            c += __shfl_xor_sync(FULLM, c, off);
        bool isLast = false;
        if (lane == 0) {
            g_contrib[blockIdx.x] = c;
            __threadfence();
            isLast = (atomicAdd(&g_count, 1) == NCTA - 1);
        }
        isLast = __shfl_sync(FULLM, isLast ? 1 : 0, 0) != 0;
        if (isLast) {
            __threadfence();
            float ssum = 0.0f;
            #pragma unroll
            for (int k = 0; k < NCTA / 32; k++)
                ssum += g_contrib[lane + 32 * k];
            #pragma unroll
            for (int off = 16; off > 0; off >>= 1)
                ssum += __shfl_down_sync(FULLM, ssum, off);
            if (lane == 0) {
                out[(size_t)NTOK * DD] = ssum;
                g_count = 0;                  // reset for next graph replay
            }
        }
    }
}

extern "C" void kernel_launch(void* const* d_in, const int* in_sizes, int n_in,
                              void* d_out, int out_size) {
    const float* x        = (const float*)d_in[0];
    const float* eo       = (const float*)d_in[1];
    const float* rewards  = (const float*)d_in[2];
    const float* W        = (const float*)d_in[3];
    const float* bias     = (const float*)d_in[4];
    const float* baseline = (const float*)d_in[5];
    const float* noise_u  = (const float*)d_in[6];
    float* out = (float*)d_out;

    rlgate_kernel<<<NCTA, 256>>>(x, eo, rewards, W, bias, baseline, noise_u, out);
}